// round 17
// baseline (speedup 1.0000x reference)
#include <cuda_runtime.h>

#define NQ 65536   // queries
#define DD 128     // dims
#define KK 1024    // codes
#define ASTR 68    // floats per As k-row (64 q + pad), 272B: 16B-aligned
#define BSTR 132   // floats per Bs k-row (128 c + pad)

typedef unsigned long long ull;

__device__ __forceinline__ void fma2(ull& d, ull a, ull b) {
    asm("fma.rn.f32x2 %0, %1, %2, %0;" : "+l"(d) : "l"(a), "l"(b));
}
__device__ __forceinline__ ull dup2(float a) {
    ull r;
    asm("mov.b64 %0, {%1, %1};" : "=l"(r) : "f"(a));
    return r;
}
__device__ __forceinline__ void unpack2(ull v, float& lo, float& hi) {
    asm("mov.b64 {%0, %1}, %2;" : "=f"(lo), "=f"(hi) : "l"(v));
}

// R17: R8's proven per-warp balance (8q x 8c, 32 FFMA2 per 6 LDS) at HIGHER
// occupancy via smaller CTAs: 128 threads = 16 tx * 8 ty, CTA = 64 queries
// x 1024 codes (8 blocks of 128). Target 5 CTAs/SM (20 warps, 5/SMSP) vs
// R8's 16 warps. Staging/loop structure is R8-verbatim.
__global__ __launch_bounds__(128, 5) void vq_kernel(
    const float* __restrict__ z, const float* __restrict__ cb,
    float* __restrict__ out) {
    __shared__ float As[16 * ASTR];   // [k][q] staged query tile (64 q)
    __shared__ float Bs[16 * BSTR];   // [k][c] staged code tile (128 c)
    __shared__ float c2s[KK];
    __shared__ float z2s[64];

    const int tid = threadIdx.x;
    const int tx = tid & 15;
    const int ty = tid >> 4;          // 0..7
    const int q0 = blockIdx.x * 64;

    // ---- c2s: ||c||^2 for all 1024 codes (8 per thread)
#pragma unroll
    for (int j = 0; j < 8; ++j) {
        const int c = tid + j * 128;
        float s = 0.f;
#pragma unroll 8
        for (int k4 = 0; k4 < 32; ++k4) {
            const float4 v =
                *reinterpret_cast<const float4*>(&cb[c * DD + k4 * 4]);
            s = fmaf(v.x, v.x, s); s = fmaf(v.y, v.y, s);
            s = fmaf(v.z, v.z, s); s = fmaf(v.w, v.w, s);
        }
        c2s[c] = s;
    }
    // ---- z2s: ||z||^2 (only for the reference's ulp-grid tie-break)
    if (tid < 64) {
        float s = 0.f;
#pragma unroll 8
        for (int k4 = 0; k4 < 32; ++k4) {
            const float4 v = *reinterpret_cast<const float4*>(
                &z[(q0 + tid) * DD + k4 * 4]);
            s = fmaf(v.x, v.x, s); s = fmaf(v.y, v.y, s);
            s = fmaf(v.z, v.z, s); s = fmaf(v.w, v.w, s);
        }
        z2s[tid] = s;
    }

    float v0[8], v1[8];
    int i0[8], i1[8];
#pragma unroll
    for (int q = 0; q < 8; ++q) {
        v0[q] = 3.4e38f; v1[q] = 3.4e38f; i0[q] = 0; i1[q] = 0;
    }

    for (int cblk = 0; cblk < 8; ++cblk) {
        ull acc[8][4];
#pragma unroll
        for (int q = 0; q < 8; ++q)
#pragma unroll
            for (int p = 0; p < 4; ++p) acc[q][p] = 0ull;

        for (int kc = 0; kc < 8; ++kc) {
            __syncthreads();  // prior readers done (covers c2s/z2s at first)
            // ---- Stage As: 64 q x 16 dims, transposed to [k][q]. 2 f4/thr.
#pragma unroll
            for (int i = 0; i < 2; ++i) {
                const int idx = tid + i * 128;       // 0..255
                const int row = idx >> 2, d4 = idx & 3;
                const float4 va = *reinterpret_cast<const float4*>(
                    &z[(q0 + row) * DD + kc * 16 + d4 * 4]);
                As[(d4 * 4 + 0) * ASTR + row] = va.x;
                As[(d4 * 4 + 1) * ASTR + row] = va.y;
                As[(d4 * 4 + 2) * ASTR + row] = va.z;
                As[(d4 * 4 + 3) * ASTR + row] = va.w;
            }
            // ---- Stage Bs: 128 c x 16 dims, transposed to [k][c]. 4 f4/thr.
#pragma unroll
            for (int i = 0; i < 4; ++i) {
                const int idx = tid + i * 128;       // 0..511
                const int row = idx >> 2, d4 = idx & 3;
                const float4 vb = *reinterpret_cast<const float4*>(
                    &cb[(cblk * 128 + row) * DD + kc * 16 + d4 * 4]);
                Bs[(d4 * 4 + 0) * BSTR + row] = vb.x;
                Bs[(d4 * 4 + 1) * BSTR + row] = vb.y;
                Bs[(d4 * 4 + 2) * BSTR + row] = vb.z;
                Bs[(d4 * 4 + 3) * BSTR + row] = vb.w;
            }
            __syncthreads();

            // ---- R8 inner loop verbatim (queries split 0..31 / 32..63)
#pragma unroll 4
            for (int k = 0; k < 16; ++k) {
                const float4 a0 =
                    *reinterpret_cast<const float4*>(&As[k * ASTR + ty * 4]);
                const float4 a1 = *reinterpret_cast<const float4*>(
                    &As[k * ASTR + 32 + ty * 4]);
                const ulonglong2 b01 =
                    *reinterpret_cast<const ulonglong2*>(&Bs[k * BSTR + tx * 4]);
                const ulonglong2 b23 = *reinterpret_cast<const ulonglong2*>(
                    &Bs[k * BSTR + 64 + tx * 4]);
                const ull aa[8] = {dup2(a0.x), dup2(a0.y), dup2(a0.z),
                                   dup2(a0.w), dup2(a1.x), dup2(a1.y),
                                   dup2(a1.z), dup2(a1.w)};
                const ull bb[4] = {b01.x, b01.y, b23.x, b23.y};
#pragma unroll
                for (int q = 0; q < 8; ++q)
#pragma unroll
                    for (int p = 0; p < 4; ++p) fma2(acc[q][p], aa[q], bb[p]);
            }
        }

        // ---- scores; ascending code order per query (first-occurrence top-2)
        const int cbase = cblk * 128;
#pragma unroll
        for (int q = 0; q < 8; ++q) {
#pragma unroll
            for (int p = 0; p < 4; ++p) {
                const int cc = cbase + ((p < 2) ? (tx * 4 + p * 2)
                                                : (64 + tx * 4 + (p - 2) * 2));
                float dlo, dhi;
                unpack2(acc[q][p], dlo, dhi);
                const float mlo = fmaf(-2.f, dlo, c2s[cc]);
                const float mhi = fmaf(-2.f, dhi, c2s[cc + 1]);
                if (mlo < v0[q]) {
                    v1[q] = v0[q]; i1[q] = i0[q]; v0[q] = mlo; i0[q] = cc;
                } else if (mlo < v1[q]) { v1[q] = mlo; i1[q] = cc; }
                if (mhi < v0[q]) {
                    v1[q] = v0[q]; i1[q] = i0[q]; v0[q] = mhi; i0[q] = cc + 1;
                } else if (mhi < v1[q]) { v1[q] = mhi; i1[q] = cc + 1; }
            }
        }
    }

    // ---- merge top-2 across the 16 tx lanes (warp = 16 tx x 2 ty)
#pragma unroll
    for (int off = 1; off < 16; off <<= 1) {
#pragma unroll
        for (int q = 0; q < 8; ++q) {
            const float w0 = __shfl_xor_sync(0xffffffffu, v0[q], off);
            const int j0 = __shfl_xor_sync(0xffffffffu, i0[q], off);
            const float w1 = __shfl_xor_sync(0xffffffffu, v1[q], off);
            const int j1 = __shfl_xor_sync(0xffffffffu, i1[q], off);
            if (w0 < v0[q] || (w0 == v0[q] && j0 < i0[q])) {
                v1[q] = v0[q]; i1[q] = i0[q]; v0[q] = w0; i0[q] = j0;
            } else if (w0 < v1[q] || (w0 == v1[q] && j0 < i1[q])) {
                v1[q] = w0; i1[q] = j0;
            }
            if (w1 < v0[q] || (w1 == v0[q] && j1 < i0[q])) {
                v1[q] = v0[q]; i1[q] = i0[q]; v0[q] = w1; i0[q] = j1;
            } else if (w1 < v1[q] || (w1 == v1[q] && j1 < i1[q])) {
                v1[q] = w1; i1[q] = j1;
            }
        }
    }

    if (tx == 0) {
#pragma unroll
        for (int q = 0; q < 8; ++q) {
            const int lq = (q < 4) ? (ty * 4 + q) : (32 + ty * 4 + (q - 4));
            // Reference dist2 = (z2-2dot)+c2 quantized at ulp(z2+score):
            // within one grid step the reference ties -> argmin takes lower idx.
            const float sfull = z2s[lq] + v0[q];
            const int ebits = (__float_as_int(sfull) >> 23) & 0xff;
            const float u = __int_as_float((ebits - 23) << 23);
            int win = i0[q];
            if (v1[q] - v0[q] <= u && i1[q] < i0[q]) win = i1[q];
            out[q0 + lq] = (float)win;
        }
    }
}

extern "C" void kernel_launch(void* const* d_in, const int* in_sizes, int n_in,
                              void* d_out, int out_size) {
    const float* z  = (const float*)d_in[0];
    const float* cb = (const float*)d_in[1];
    if (n_in >= 2 && in_sizes[0] == KK * DD) {  // defensive order check
        cb = (const float*)d_in[0];
        z  = (const float*)d_in[1];
    }
    vq_kernel<<<NQ / 64, 128>>>(z, cb, (float*)d_out);
}